// round 10
// baseline (speedup 1.0000x reference)
#include <cuda_runtime.h>
#include <cuda_bf16.h>

#define N_SEG 128
#define E 128
#define H 4
#define SPLIT 9
#define LOG2E 1.4426950408889634f

typedef unsigned long long ull;

// Per-(part,seg) partial outputs — every block writes its FULL slice
// unconditionally, so no zero-init pass is needed anywhere.
__device__ float g_part[SPLIT * N_SEG * H * E];   // 2.25 MB
__device__ float g_spart[SPLIT * N_SEG * H];

__device__ __forceinline__ float ex2f(float x) {
    float y;
    asm("ex2.approx.f32 %0, %1;" : "=f"(y) : "f"(x));
    return y;
}
__device__ __forceinline__ ull pack2(float a, float b) {
    ull r; asm("mov.b64 %0, {%1, %2};" : "=l"(r) : "f"(a), "f"(b)); return r;
}
__device__ __forceinline__ void unpack2(ull v, float& a, float& b) {
    asm("mov.b64 {%0, %1}, %2;" : "=f"(a), "=f"(b) : "l"(v));
}
__device__ __forceinline__ ull fma2(ull a, ull b, ull c) {
    ull d; asm("fma.rn.f32x2 %0, %1, %2, %3;" : "=l"(d) : "l"(a), "l"(b), "l"(c)); return d;
}
__device__ __forceinline__ ull mul2(ull a, ull b) {
    ull d; asm("mul.rn.f32x2 %0, %1, %2;" : "=l"(d) : "l"(a), "l"(b)); return d;
}

// ---------------------------------------------------------------------------
// Main: no init kernel. Per-block prologue: interleaved binary search for the
// two segment boundaries (MLP=2, ~18 probes, L2-resident batch) + inline
// weight load/scale. 8 rows per batch per warp; lane = float4 slice of E.
// f32x2 packed math over natural element pairs. Multi-value butterfly for
// dots; e-broadcast via double-buffered smem LDS.128 (replaces 32 SHFL/batch).
// Epilogue: atomic-free — block writes its private (part,seg) slice.
// Grid: (N_SEG, SPLIT), 256 threads (8 warps).
// ---------------------------------------------------------------------------
__global__ void __launch_bounds__(256, 2)
main_kernel(const float* __restrict__ x, const float* __restrict__ weights,
            const int* __restrict__ batch, int N) {
    const int seg  = blockIdx.x;
    const int part = blockIdx.y;

    // ---- interleaved binary search: lo = lower_bound(seg), hi = lb(seg+1) ----
    int p1 = 0, p2 = 0;
    #pragma unroll 1
    for (int step = 131072; step > 0; step >>= 1) {   // 2^17 < N=250000 < 2^18? use two top steps
        int q1 = p1 + step, q2 = p2 + step;
        int b1 = (q1 <= N) ? batch[q1 - 1] : N_SEG;
        int b2 = (q2 <= N) ? batch[q2 - 1] : N_SEG;
        if (b1 < seg)     p1 = q1;
        if (b2 < seg + 1) p2 = q2;
    }
    // handle N beyond 2^17: one extra top-level step of 131072 already covered
    // since 250000 < 2*131072; add second pass for the residual bit:
    {
        int step = 131072;
        int q1 = p1 + step, q2 = p2 + step;
        if (q1 <= N && batch[q1 - 1] < seg)     p1 = q1;
        if (q2 <= N && batch[q2 - 1] < seg + 1) p2 = q2;
        for (step = 65536; step > 0; step >>= 1) {
            q1 = p1 + step; q2 = p2 + step;
            int b1 = (q1 <= N) ? batch[q1 - 1] : N_SEG;
            int b2 = (q2 <= N) ? batch[q2 - 1] : N_SEG;
            if (b1 < seg)     p1 = q1;
            if (b2 < seg + 1) p2 = q2;
        }
    }
    const int lo = p1, hi = p2;
    const int len = hi - lo;
    const int rlo = lo + (int)((long long)len * part / SPLIT);
    const int rhi = lo + (int)((long long)len * (part + 1) / SPLIT);

    const int warp = threadIdx.x >> 5;
    const int lane = threadIdx.x & 31;

    // ---- inline weight load + log2e scale, packed element pairs ----
    const float* wl = weights + (lane << 2);
    ull wp[H][2];
    #pragma unroll
    for (int h = 0; h < H; h++) {
        wp[h][0] = pack2(wl[h * E + 0] * LOG2E, wl[h * E + 1] * LOG2E);
        wp[h][1] = pack2(wl[h * E + 2] * LOG2E, wl[h * E + 3] * LOG2E);
    }

    ull acc[H][2];
    #pragma unroll
    for (int h = 0; h < H; h++) { acc[h][0] = 0ull; acc[h][1] = 0ull; }
    float s = 0.f;                     // this lane: head (lane&3), rows (lane>>2)

    const int myrow = lane >> 2;

    __shared__ float e_sh[8][2][32];   // per-warp double-buffered e broadcast
    int pbuf = 0;

    for (int base = rlo + warp * 8; base < rhi; base += 64) {
        // ---- load up to 8 rows (MLP=8) ----
        float4 xr[8];
        #pragma unroll
        for (int i = 0; i < 8; i++) {
            const int rr = base + i;
            if (rr < rhi)
                xr[i] = *(const float4*)(x + (size_t)rr * E + (lane << 2));
            else
                xr[i] = make_float4(0.f, 0.f, 0.f, 0.f);
        }

        // ---- 32 dot partials via packed FFMA2 ----
        float vals[32];
        ull xlo[8], xhi[8];
        #pragma unroll
        for (int i = 0; i < 8; i++) {
            xlo[i] = pack2(xr[i].x, xr[i].y);
            xhi[i] = pack2(xr[i].z, xr[i].w);
            #pragma unroll
            for (int h = 0; h < H; h++) {
                ull d = mul2(xlo[i], wp[h][0]);
                d = fma2(xhi[i], wp[h][1], d);
                float dl, dh;
                unpack2(d, dl, dh);
                vals[i * 4 + h] = dl + dh;
            }
        }

        // ---- multi-value butterfly: 31 SHFL -> lane l holds full dot l ----
        #pragma unroll
        for (int o = 16; o >= 1; o >>= 1) {
            #pragma unroll
            for (int i = 0; i < o; i++) {
                const bool up = (lane & o) != 0;
                float give = up ? vals[i] : vals[i + o];
                float keep = up ? vals[i + o] : vals[i];
                vals[i] = keep + __shfl_xor_sync(0xFFFFFFFFu, give, o);
            }
        }

        // ---- one ex2 per lane; zero invalid rows ----
        float e = ex2f(vals[0]);
        if (base + myrow >= rhi) e = 0.f;
        s += e;

        // ---- smem e-broadcast (double-buffered, one syncwarp) ----
        e_sh[warp][pbuf][lane] = e;
        __syncwarp();

        #pragma unroll
        for (int i = 0; i < 8; i++) {
            const float4 ev = *(const float4*)&e_sh[warp][pbuf][i * 4];
            const ull eb0 = pack2(ev.x, ev.x);
            const ull eb1 = pack2(ev.y, ev.y);
            const ull eb2 = pack2(ev.z, ev.z);
            const ull eb3 = pack2(ev.w, ev.w);
            acc[0][0] = fma2(eb0, xlo[i], acc[0][0]); acc[0][1] = fma2(eb0, xhi[i], acc[0][1]);
            acc[1][0] = fma2(eb1, xlo[i], acc[1][0]); acc[1][1] = fma2(eb1, xhi[i], acc[1][1]);
            acc[2][0] = fma2(eb2, xlo[i], acc[2][0]); acc[2][1] = fma2(eb2, xhi[i], acc[2][1]);
            acc[3][0] = fma2(eb3, xlo[i], acc[3][0]); acc[3][1] = fma2(eb3, xhi[i], acc[3][1]);
        }
        pbuf ^= 1;
    }

    // collapse s over lanes sharing a head: lanes 0..3 end with heads 0..3
    s += __shfl_xor_sync(0xFFFFFFFFu, s, 4);
    s += __shfl_xor_sync(0xFFFFFFFFu, s, 8);
    s += __shfl_xor_sync(0xFFFFFFFFu, s, 16);

    // -----------------------------------------------------------------------
    // Block reduction in smem, then plain stores to the block's private slice.
    // -----------------------------------------------------------------------
    __shared__ float sacc[8][H * E];   // 16 KB
    __shared__ float ssum_sh[8][H];

    float4* dst = (float4*)&sacc[warp][0];
    #pragma unroll
    for (int h = 0; h < H; h++) {
        float4 v;
        unpack2(acc[h][0], v.x, v.y);
        unpack2(acc[h][1], v.z, v.w);
        dst[h * 32 + lane] = v;
    }
    if (lane < H) ssum_sh[warp][lane] = s;
    __syncthreads();

    const int slot = part * N_SEG + seg;
    if (threadIdx.x < 128) {
        const int i = threadIdx.x;  // float4 index into H*E/4 = 128
        float4 a4 = ((const float4*)sacc[0])[i];
        #pragma unroll
        for (int w8 = 1; w8 < 8; w8++) {
            float4 t = ((const float4*)sacc[w8])[i];
            a4.x += t.x; a4.y += t.y; a4.z += t.z; a4.w += t.w;
        }
        ((float4*)(g_part + (size_t)slot * (H * E)))[i] = a4;
    } else if (threadIdx.x < 128 + H) {
        const int h = threadIdx.x - 128;
        float sv = 0.f;
        #pragma unroll
        for (int w8 = 0; w8 < 8; w8++) sv += ssum_sh[w8][h];
        g_spart[slot * H + h] = sv;
    }
}

// ---------------------------------------------------------------------------
// Finalize: sum partials over parts, divide, average heads.
// out[b,e] = (1/H) * sum_h (sum_p part[p,b,h,e]) / (sum_p spart[p,b,h])
// ---------------------------------------------------------------------------
__global__ void final_kernel(float* __restrict__ out) {
    const int b = blockIdx.x;
    const int e = threadIdx.x;

    float sh[H];
    #pragma unroll
    for (int h = 0; h < H; h++) sh[h] = 0.f;
    #pragma unroll
    for (int p = 0; p < SPLIT; p++) {
        const float* sp = g_spart + (p * N_SEG + b) * H;
        #pragma unroll
        for (int h = 0; h < H; h++) sh[h] += sp[h];
    }

    float acc = 0.f;
    #pragma unroll
    for (int h = 0; h < H; h++) {
        float v = 0.f;
        #pragma unroll
        for (int p = 0; p < SPLIT; p++)
            v += g_part[(size_t)(p * N_SEG + b) * (H * E) + h * E + e];
        if (sh[h] > 0.f) acc += v / sh[h];
    }
    out[b * E + e] = acc * (1.0f / H);
}

extern "C" void kernel_launch(void* const* d_in, const int* in_sizes, int n_in,
                              void* d_out, int out_size) {
    const float* x       = (const float*)d_in[0];
    const float* weights = (const float*)d_in[1];
    const int*   batch   = (const int*)d_in[2];
    float* out = (float*)d_out;
    const int N = in_sizes[0] / E;

    main_kernel<<<dim3(N_SEG, SPLIT), 256>>>(x, weights, batch, N);
    final_kernel<<<N_SEG, E>>>(out);
}

// round 12
// speedup vs baseline: 1.6151x; 1.6151x over previous
#include <cuda_runtime.h>
#include <cuda_bf16.h>

#define N_SEG 128
#define E 128
#define H 4
#define SPLIT 9
#define LOG2E 1.4426950408889634f

typedef unsigned long long ull;

__device__ float g_w2[H * E];              // weights pre-scaled by log2(e)
__device__ float g_hsum[N_SEG * H * E];    // unnormalized weighted sums
__device__ float g_ssum[N_SEG * H];        // unnormalized softmax denominators
__device__ int   g_segoff[N_SEG + 1];      // segment boundaries

__device__ __forceinline__ float ex2f(float x) {
    float y;
    asm("ex2.approx.f32 %0, %1;" : "=f"(y) : "f"(x));
    return y;
}
__device__ __forceinline__ ull pack2(float a, float b) {
    ull r; asm("mov.b64 %0, {%1, %2};" : "=l"(r) : "f"(a), "f"(b)); return r;
}
__device__ __forceinline__ void unpack2(ull v, float& a, float& b) {
    asm("mov.b64 {%0, %1}, %2;" : "=f"(a), "=f"(b) : "l"(v));
}
__device__ __forceinline__ ull fma2(ull a, ull b, ull c) {
    ull d; asm("fma.rn.f32x2 %0, %1, %2, %3;" : "=l"(d) : "l"(a), "l"(b), "l"(c)); return d;
}
__device__ __forceinline__ ull mul2(ull a, ull b) {
    ull d; asm("mul.rn.f32x2 %0, %1, %2;" : "=l"(d) : "l"(a), "l"(b)); return d;
}

// ---------------------------------------------------------------------------
// Init: zero accumulators (float4), scale weights, vectorized boundary scan.
// (identical to R9 — proven)
// ---------------------------------------------------------------------------
__global__ void init_kernel(const float* __restrict__ weights,
                            const int* __restrict__ batch, int N) {
    int bid = blockIdx.x;
    int tid = threadIdx.x;
    if (bid < 65) {
        int idx = bid * 256 + tid;      // float4 index
        if (idx < 16384) {
            ((float4*)g_hsum)[idx] = make_float4(0.f, 0.f, 0.f, 0.f);
        } else if (idx < 16512) {
            ((float4*)g_ssum)[idx - 16384] = make_float4(0.f, 0.f, 0.f, 0.f);
        }
    } else if (bid == 65) {
        for (int i = tid; i < H * E; i += 256)
            g_w2[i] = weights[i] * LOG2E;
    } else {
        int t = (bid - 66) * 256 + tid;
        int i = t * 4;
        if (i < N) {
            int4 v = ((const int4*)batch)[t];
            int nxt = (i + 4 < N) ? batch[i + 4] : N_SEG;
            if (i == 0)
                for (int b = 0; b <= v.x; b++) g_segoff[b] = 0;
            for (int b = v.x + 1; b <= v.y; b++) g_segoff[b] = i + 1;
            for (int b = v.y + 1; b <= v.z; b++) g_segoff[b] = i + 2;
            for (int b = v.z + 1; b <= v.w; b++) g_segoff[b] = i + 3;
            for (int b = v.w + 1; b <= nxt; b++) g_segoff[b] = i + 4;
        }
    }
}

// ---------------------------------------------------------------------------
// Main: 4 rows per batch per warp, software-pipelined (next batch's loads
// issue before current batch's compute). Lane = float4 slice of E; f32x2
// packed math over natural element pairs.
// Butterfly reduces 16 values (4 rows x 4 heads): 4 stages with shuffle
// offsets {16,8,4,2} reduce lane bits 4..1, then ONE extra xor-1 add
// completes the reduction over lane bit 0 (R11's missing stage). After:
// lanes 2k,2k+1 BOTH hold the complete dot of value k (row k>>2, head k&3).
// One ex2 per lane. Grid: (N_SEG, SPLIT), 256 threads (8 warps).
// ---------------------------------------------------------------------------
__global__ void __launch_bounds__(256, 2)
main_kernel(const float* __restrict__ x) {
    const int seg  = blockIdx.x;
    const int part = blockIdx.y;
    const int lo   = g_segoff[seg];
    const int hi   = g_segoff[seg + 1];
    const int len  = hi - lo;
    const int rlo  = lo + (int)((long long)len * part / SPLIT);
    const int rhi  = lo + (int)((long long)len * (part + 1) / SPLIT);

    const int warp = threadIdx.x >> 5;
    const int lane = threadIdx.x & 31;

    // Pre-packed per-lane weight element-pairs for all 4 heads
    const float* wl = g_w2 + (lane << 2);
    ull wp[H][2];
    #pragma unroll
    for (int h = 0; h < H; h++) {
        wp[h][0] = pack2(wl[h * E + 0], wl[h * E + 1]);
        wp[h][1] = pack2(wl[h * E + 2], wl[h * E + 3]);
    }

    ull acc[H][2];
    #pragma unroll
    for (int h = 0; h < H; h++) { acc[h][0] = 0ull; acc[h][1] = 0ull; }
    float s = 0.f;

    // this lane's value k = lane>>1 after the butterfly
    const int myrow = lane >> 3;           // row of value k = k>>2 (0..3)

    int base = rlo + warp * 4;
    float4 xr[4];
    #pragma unroll
    for (int i = 0; i < 4; i++) {
        const int rr = base + i;
        xr[i] = (rr < rhi) ? *(const float4*)(x + (size_t)rr * E + (lane << 2))
                           : make_float4(0.f, 0.f, 0.f, 0.f);
    }

    while (base < rhi) {
        const int nbase = base + 32;       // 8 warps x 4 rows
        // ---- prefetch next batch (overlaps with compute below) ----
        float4 xn[4];
        #pragma unroll
        for (int i = 0; i < 4; i++) {
            const int rr = nbase + i;
            xn[i] = (rr < rhi) ? *(const float4*)(x + (size_t)rr * E + (lane << 2))
                               : make_float4(0.f, 0.f, 0.f, 0.f);
        }

        // ---- 16 dot partials via packed FFMA2 ----
        ull xlo[4], xhi[4];
        float vals[16];
        #pragma unroll
        for (int i = 0; i < 4; i++) {
            xlo[i] = pack2(xr[i].x, xr[i].y);
            xhi[i] = pack2(xr[i].z, xr[i].w);
            #pragma unroll
            for (int h = 0; h < H; h++) {
                ull d = mul2(xlo[i], wp[h][0]);
                d = fma2(xhi[i], wp[h][1], d);
                float dl, dh;
                unpack2(d, dl, dh);
                vals[i * 4 + h] = dl + dh;
            }
        }

        // ---- multi-value butterfly over lane bits 4..1 (15 SHFL) ----
        #pragma unroll
        for (int d = 8; d >= 1; d >>= 1) {
            #pragma unroll
            for (int i = 0; i < d; i++) {
                const bool up = (lane & (d << 1)) != 0;
                float give = up ? vals[i] : vals[i + d];
                float keep = up ? vals[i + d] : vals[i];
                vals[i] = keep + __shfl_xor_sync(0xFFFFFFFFu, give, d << 1);
            }
        }
        // ---- final stage: reduce lane bit 0 (completes all 32 lanes) ----
        vals[0] += __shfl_xor_sync(0xFFFFFFFFu, vals[0], 1);

        // ---- one ex2 per lane; zero invalid rows ----
        float e = ex2f(vals[0]);
        if (base + myrow >= rhi) e = 0.f;
        s += e;

        // ---- broadcast e per (row,head), packed accumulate ----
        #pragma unroll
        for (int i = 0; i < 4; i++) {
            const float e0 = __shfl_sync(0xFFFFFFFFu, e, (i * 4 + 0) << 1);
            const float e1 = __shfl_sync(0xFFFFFFFFu, e, (i * 4 + 1) << 1);
            const float e2 = __shfl_sync(0xFFFFFFFFu, e, (i * 4 + 2) << 1);
            const float e3 = __shfl_sync(0xFFFFFFFFu, e, (i * 4 + 3) << 1);
            const ull eb0 = pack2(e0, e0);
            const ull eb1 = pack2(e1, e1);
            const ull eb2 = pack2(e2, e2);
            const ull eb3 = pack2(e3, e3);
            acc[0][0] = fma2(eb0, xlo[i], acc[0][0]); acc[0][1] = fma2(eb0, xhi[i], acc[0][1]);
            acc[1][0] = fma2(eb1, xlo[i], acc[1][0]); acc[1][1] = fma2(eb1, xhi[i], acc[1][1]);
            acc[2][0] = fma2(eb2, xlo[i], acc[2][0]); acc[2][1] = fma2(eb2, xhi[i], acc[2][1]);
            acc[3][0] = fma2(eb3, xlo[i], acc[3][0]); acc[3][1] = fma2(eb3, xhi[i], acc[3][1]);
        }

        base = nbase;
        xr[0] = xn[0]; xr[1] = xn[1]; xr[2] = xn[2]; xr[3] = xn[3];
    }

    // collapse s over rows (value bits 3,2 live in lane bits 4,3):
    // afterwards lanes sharing head bits (lane bits 2,1) hold that head's
    // total; head h is available at lane 2h.
    s += __shfl_xor_sync(0xFFFFFFFFu, s, 8);
    s += __shfl_xor_sync(0xFFFFFFFFu, s, 16);

    // -----------------------------------------------------------------------
    // Atomic-free block reduction: per-warp shared slices, tree reduce,
    // one global atomicAdd pass.
    // -----------------------------------------------------------------------
    __shared__ float sacc[8][H * E];   // 16 KB
    __shared__ float ssum_sh[8][H];

    float4* dst = (float4*)&sacc[warp][0];
    #pragma unroll
    for (int h = 0; h < H; h++) {
        float4 v;
        unpack2(acc[h][0], v.x, v.y);
        unpack2(acc[h][1], v.z, v.w);
        dst[h * 32 + lane] = v;
    }
    if (lane < 8 && (lane & 1) == 0) ssum_sh[warp][lane >> 1] = s;
    __syncthreads();

    if (threadIdx.x < 128) {
        const int i = threadIdx.x;  // float4 index into H*E/4 = 128
        float4 a4 = ((const float4*)sacc[0])[i];
        #pragma unroll
        for (int w8 = 1; w8 < 8; w8++) {
            float4 t = ((const float4*)sacc[w8])[i];
            a4.x += t.x; a4.y += t.y; a4.z += t.z; a4.w += t.w;
        }
        float* gh = g_hsum + seg * (H * E) + i * 4;
        atomicAdd(gh + 0, a4.x);
        atomicAdd(gh + 1, a4.y);
        atomicAdd(gh + 2, a4.z);
        atomicAdd(gh + 3, a4.w);
    } else if (threadIdx.x < 128 + H) {
        const int h = threadIdx.x - 128;
        float sv = 0.f;
        #pragma unroll
        for (int w8 = 0; w8 < 8; w8++) sv += ssum_sh[w8][h];
        atomicAdd(&g_ssum[seg * H + h], sv);
    }
}

// ---------------------------------------------------------------------------
// Finalize: out[b,e] = (1/H) * sum_h hsum[b,h,e] / ssum[b,h]
// ---------------------------------------------------------------------------
__global__ void final_kernel(float* __restrict__ out) {
    const int b = blockIdx.x;
    const int e = threadIdx.x;
    const float* hs = g_hsum + b * (H * E);
    const float* ss = g_ssum + b * H;
    float acc = 0.f;
    #pragma unroll
    for (int h = 0; h < H; h++) {
        const float s = ss[h];
        if (s > 0.f) acc += hs[h * E + e] / s;
    }
    out[b * E + e] = acc * (1.0f / H);
}

extern "C" void kernel_launch(void* const* d_in, const int* in_sizes, int n_in,
                              void* d_out, int out_size) {
    const float* x       = (const float*)d_in[0];
    const float* weights = (const float*)d_in[1];
    const int*   batch   = (const int*)d_in[2];
    float* out = (float*)d_out;
    const int N = in_sizes[0] / E;

    const int scan_blocks = (N + 1023) / 1024;   // int4 per thread
    init_kernel<<<66 + scan_blocks, 256>>>(weights, batch, N);
    main_kernel<<<dim3(N_SEG, SPLIT), 256>>>(x);
    final_kernel<<<N_SEG, E>>>(out);
}

// round 13
// speedup vs baseline: 1.6379x; 1.0141x over previous
#include <cuda_runtime.h>
#include <cuda_bf16.h>

#define N_SEG 128
#define E 128
#define H 4
#define SPLIT 10
#define LOG2E 1.4426950408889634f

typedef unsigned long long ull;

__device__ float g_w2[H * E];              // weights pre-scaled by log2(e)
__device__ float g_hsum[N_SEG * H * E];    // unnormalized weighted sums
__device__ float g_ssum[N_SEG * H];        // unnormalized softmax denominators
__device__ int   g_segoff[N_SEG + 1];      // segment boundaries

__device__ __forceinline__ float ex2f(float x) {
    float y;
    asm("ex2.approx.f32 %0, %1;" : "=f"(y) : "f"(x));
    return y;
}
__device__ __forceinline__ ull pack2(float a, float b) {
    ull r; asm("mov.b64 %0, {%1, %2};" : "=l"(r) : "f"(a), "f"(b)); return r;
}
__device__ __forceinline__ void unpack2(ull v, float& a, float& b) {
    asm("mov.b64 {%0, %1}, %2;" : "=f"(a), "=f"(b) : "l"(v));
}
__device__ __forceinline__ ull fma2(ull a, ull b, ull c) {
    ull d; asm("fma.rn.f32x2 %0, %1, %2, %3;" : "=l"(d) : "l"(a), "l"(b), "l"(c)); return d;
}
__device__ __forceinline__ ull mul2(ull a, ull b) {
    ull d; asm("mul.rn.f32x2 %0, %1, %2;" : "=l"(d) : "l"(a), "l"(b)); return d;
}

// ---------------------------------------------------------------------------
// Init: zero accumulators (float4), scale weights, vectorized boundary scan.
// (identical to R9 — proven)
// ---------------------------------------------------------------------------
__global__ void init_kernel(const float* __restrict__ weights,
                            const int* __restrict__ batch, int N) {
    int bid = blockIdx.x;
    int tid = threadIdx.x;
    if (bid < 65) {
        int idx = bid * 256 + tid;      // float4 index
        if (idx < 16384) {
            ((float4*)g_hsum)[idx] = make_float4(0.f, 0.f, 0.f, 0.f);
        } else if (idx < 16512) {
            ((float4*)g_ssum)[idx - 16384] = make_float4(0.f, 0.f, 0.f, 0.f);
        }
    } else if (bid == 65) {
        for (int i = tid; i < H * E; i += 256)
            g_w2[i] = weights[i] * LOG2E;
    } else {
        int t = (bid - 66) * 256 + tid;
        int i = t * 4;
        if (i < N) {
            int4 v = ((const int4*)batch)[t];
            int nxt = (i + 4 < N) ? batch[i + 4] : N_SEG;
            if (i == 0)
                for (int b = 0; b <= v.x; b++) g_segoff[b] = 0;
            for (int b = v.x + 1; b <= v.y; b++) g_segoff[b] = i + 1;
            for (int b = v.y + 1; b <= v.z; b++) g_segoff[b] = i + 2;
            for (int b = v.z + 1; b <= v.w; b++) g_segoff[b] = i + 3;
            for (int b = v.w + 1; b <= nxt; b++) g_segoff[b] = i + 4;
        }
    }
}

// ---------------------------------------------------------------------------
// Main: 4 rows per batch per warp, NO explicit pipelining (R12 showed it
// neutral), __launch_bounds__(256,3) -> 24 warps/SM to cover SHFL/memory
// stall chains (the R12-inferred bottleneck). Lane = float4 slice of E;
// f32x2 packed math over natural element pairs.
// Butterfly (proven in R12): 4 stages offsets {16,8,4,2} + final xor-1;
// after, lanes 2k,2k+1 hold complete dot of value k (row k>>2, head k&3).
// Grid: (N_SEG, SPLIT), 256 threads (8 warps).
// ---------------------------------------------------------------------------
__global__ void __launch_bounds__(256, 3)
main_kernel(const float* __restrict__ x) {
    const int seg  = blockIdx.x;
    const int part = blockIdx.y;
    const int lo   = g_segoff[seg];
    const int hi   = g_segoff[seg + 1];
    const int len  = hi - lo;
    const int rlo  = lo + (int)((long long)len * part / SPLIT);
    const int rhi  = lo + (int)((long long)len * (part + 1) / SPLIT);

    const int warp = threadIdx.x >> 5;
    const int lane = threadIdx.x & 31;

    // Pre-packed per-lane weight element-pairs for all 4 heads
    const float* wl = g_w2 + (lane << 2);
    ull wp[H][2];
    #pragma unroll
    for (int h = 0; h < H; h++) {
        wp[h][0] = pack2(wl[h * E + 0], wl[h * E + 1]);
        wp[h][1] = pack2(wl[h * E + 2], wl[h * E + 3]);
    }

    ull acc[H][2];
    #pragma unroll
    for (int h = 0; h < H; h++) { acc[h][0] = 0ull; acc[h][1] = 0ull; }
    float s = 0.f;

    const int myrow = lane >> 3;           // row of this lane's value k = lane>>1

    for (int base = rlo + warp * 4; base < rhi; base += 32) {
        // ---- load 4 rows ----
        ull xlo[4], xhi[4];
        #pragma unroll
        for (int i = 0; i < 4; i++) {
            const int rr = base + i;
            float4 v = (rr < rhi)
                ? *(const float4*)(x + (size_t)rr * E + (lane << 2))
                : make_float4(0.f, 0.f, 0.f, 0.f);
            xlo[i] = pack2(v.x, v.y);
            xhi[i] = pack2(v.z, v.w);
        }

        // ---- 16 dot partials via packed FFMA2 ----
        float vals[16];
        #pragma unroll
        for (int i = 0; i < 4; i++) {
            #pragma unroll
            for (int h = 0; h < H; h++) {
                ull d = mul2(xlo[i], wp[h][0]);
                d = fma2(xhi[i], wp[h][1], d);
                float dl, dh;
                unpack2(d, dl, dh);
                vals[i * 4 + h] = dl + dh;
            }
        }

        // ---- multi-value butterfly over lane bits 4..1 (15 SHFL) ----
        #pragma unroll
        for (int d = 8; d >= 1; d >>= 1) {
            #pragma unroll
            for (int i = 0; i < d; i++) {
                const bool up = (lane & (d << 1)) != 0;
                float give = up ? vals[i] : vals[i + d];
                float keep = up ? vals[i + d] : vals[i];
                vals[i] = keep + __shfl_xor_sync(0xFFFFFFFFu, give, d << 1);
            }
        }
        // ---- final stage: reduce lane bit 0 ----
        vals[0] += __shfl_xor_sync(0xFFFFFFFFu, vals[0], 1);

        // ---- one ex2 per lane; zero invalid rows ----
        float e = ex2f(vals[0]);
        if (base + myrow >= rhi) e = 0.f;
        s += e;

        // ---- broadcast e per (row,head), packed accumulate ----
        #pragma unroll
        for (int i = 0; i < 4; i++) {
            const float e0 = __shfl_sync(0xFFFFFFFFu, e, (i * 4 + 0) << 1);
            const float e1 = __shfl_sync(0xFFFFFFFFu, e, (i * 4 + 1) << 1);
            const float e2 = __shfl_sync(0xFFFFFFFFu, e, (i * 4 + 2) << 1);
            const float e3 = __shfl_sync(0xFFFFFFFFu, e, (i * 4 + 3) << 1);
            const ull eb0 = pack2(e0, e0);
            const ull eb1 = pack2(e1, e1);
            const ull eb2 = pack2(e2, e2);
            const ull eb3 = pack2(e3, e3);
            acc[0][0] = fma2(eb0, xlo[i], acc[0][0]); acc[0][1] = fma2(eb0, xhi[i], acc[0][1]);
            acc[1][0] = fma2(eb1, xlo[i], acc[1][0]); acc[1][1] = fma2(eb1, xhi[i], acc[1][1]);
            acc[2][0] = fma2(eb2, xlo[i], acc[2][0]); acc[2][1] = fma2(eb2, xhi[i], acc[2][1]);
            acc[3][0] = fma2(eb3, xlo[i], acc[3][0]); acc[3][1] = fma2(eb3, xhi[i], acc[3][1]);
        }
    }

    // collapse s over rows (value-row bits live in lane bits 4,3):
    // afterwards head h's total is available at lane 2h.
    s += __shfl_xor_sync(0xFFFFFFFFu, s, 8);
    s += __shfl_xor_sync(0xFFFFFFFFu, s, 16);

    // -----------------------------------------------------------------------
    // Atomic-free block reduction: per-warp shared slices, tree reduce,
    // one global atomicAdd pass.
    // -----------------------------------------------------------------------
    __shared__ float sacc[8][H * E];   // 16 KB
    __shared__ float ssum_sh[8][H];

    float4* dst = (float4*)&sacc[warp][0];
    #pragma unroll
    for (int h = 0; h < H; h++) {
        float4 v;
        unpack2(acc[h][0], v.x, v.y);
        unpack2(acc[h][1], v.z, v.w);
        dst[h * 32 + lane] = v;
    }
    if (lane < 8 && (lane & 1) == 0) ssum_sh[warp][lane >> 1] = s;
    __syncthreads();

    if (threadIdx.x < 128) {
        const int i = threadIdx.x;  // float4 index into H*E/4 = 128
        float4 a4 = ((const float4*)sacc[0])[i];
        #pragma unroll
        for (int w8 = 1; w8 < 8; w8++) {
            float4 t = ((const float4*)sacc[w8])[i];
            a4.x += t.x; a4.y += t.y; a4.z += t.z; a4.w += t.w;
        }
        float* gh = g_hsum + seg * (H * E) + i * 4;
        atomicAdd(gh + 0, a4.x);
        atomicAdd(gh + 1, a4.y);
        atomicAdd(gh + 2, a4.z);
        atomicAdd(gh + 3, a4.w);
    } else if (threadIdx.x < 128 + H) {
        const int h = threadIdx.x - 128;
        float sv = 0.f;
        #pragma unroll
        for (int w8 = 0; w8 < 8; w8++) sv += ssum_sh[w8][h];
        atomicAdd(&g_ssum[seg * H + h], sv);
    }
}

// ---------------------------------------------------------------------------
// Finalize: out[b,e] = (1/H) * sum_h hsum[b,h,e] / ssum[b,h]
// ---------------------------------------------------------------------------
__global__ void final_kernel(float* __restrict__ out) {
    const int b = blockIdx.x;
    const int e = threadIdx.x;
    const float* hs = g_hsum + b * (H * E);
    const float* ss = g_ssum + b * H;
    float acc = 0.f;
    #pragma unroll
    for (int h = 0; h < H; h++) {
        const float s = ss[h];
        if (s > 0.f) acc += hs[h * E + e] / s;
    }
    out[b * E + e] = acc * (1.0f / H);
}

extern "C" void kernel_launch(void* const* d_in, const int* in_sizes, int n_in,
                              void* d_out, int out_size) {
    const float* x       = (const float*)d_in[0];
    const float* weights = (const float*)d_in[1];
    const int*   batch   = (const int*)d_in[2];
    float* out = (float*)d_out;
    const int N = in_sizes[0] / E;

    const int scan_blocks = (N + 1023) / 1024;   // int4 per thread
    init_kernel<<<66 + scan_blocks, 256>>>(weights, batch, N);
    main_kernel<<<dim3(N_SEG, SPLIT), 256>>>(x);
    final_kernel<<<N_SEG, E>>>(out);
}